// round 11
// baseline (speedup 1.0000x reference)
#include <cuda_runtime.h>

// RWKV WKV single-pass warp-scan, v5: serial-4 hybrid scan.
//   a_t = d_t a_{t-1} + ek_t v_t ; b_t = d_t b_{t-1} + ek_t
//   out = sigmoid(r) * a/(b+eps),  d = exp(-exp(w)), ek = exp(k)
//
// vs v2 (151.5us): each lane owns 4 consecutive timesteps -> 21 SHFL per 128
// elements (half of v2's MIO shuffle cost), scan loads are LDS.128, so-writes
// STS.128. r never staged (sigmoid at store from regs). CBLK=16, TTILE=128.

#define B_      8
#define T_      4096
#define C_      1024
#define CBLK    16
#define TTILE   128
#define NITER   (T_ / TTILE)      // 32
#define THREADS 256
#define SROW    132               // floats per channel row (128 + pad, mult of 4)
#define REGF    (CBLK * SROW)     // 2112 floats per region
#define SMEMB   (7 * REGF * 4)    // w,k,v x 2 bufs + so = 59136 B
#define WKV_EPS 1e-6f

// Skewed address: s(ch) = 24*(ch>>2) (mult of 4 -> 16B alignment preserved).
// Writer/readback banks: (8*cl4 + 4j + tl) mod 32, all distinct per warp.
// Scan LDS.128: lanes sweep 128 consecutive floats (rotated) -> conflict-free.
__device__ __forceinline__ int saddr(int ch, int t) {
    return ch * SROW + ((t + 24 * (ch >> 2)) & 127);
}

__global__ void __launch_bounds__(THREADS, 2)
wkv_scan5(const float4* __restrict__ r, const float4* __restrict__ w,
          const float4* __restrict__ k, const float4* __restrict__ v,
          float4* __restrict__ out) {
    extern __shared__ float S[];
    float* so = S + 6 * REGF;     // output region (single buffer)

    const int tid  = threadIdx.x;
    const int lane = tid & 31;
    const int wid  = tid >> 5;    // warp owns channels 2*wid, 2*wid+1
    const int cl4  = tid & 3;     // float4 column (4 x 16B = 16 channels)
    const int tl   = tid >> 2;    // 0..63: t-rows tl and tl+64

    const int b  = blockIdx.x >> 6;               // 8 batches
    const int c0 = (blockIdx.x & 63) * CBLK;      // 64 channel blocks
    const int rowF4 = C_ / 4;                     // 256 float4 per time row
    const int gco   = (b * T_) * rowF4 + (c0 >> 2) + cl4;

    // Prefetch tile 0 (raw w,k,v; two t-rows per stream).
    float4 pw[2], pk[2], pv[2];
#pragma unroll
    for (int h = 0; h < 2; ++h) {
        const int g = gco + (tl + h * 64) * rowF4;
        pw[h] = __ldcs(&w[g]);  pk[h] = __ldcs(&k[g]);  pv[h] = __ldcs(&v[g]);
    }

    float aC[2] = {0.f, 0.f};
    float bC[2] = {0.f, 0.f};

    for (int it = 0; it < NITER; ++it) {
        const int bf = it & 1;
        float* sw = S + (0 * 2 + bf) * REGF;
        float* sk = S + (1 * 2 + bf) * REGF;
        float* sv = S + (2 * 2 + bf) * REGF;

        // ---- stage current tile (transposed, skewed; banks distinct) ----
#pragma unroll
        for (int h = 0; h < 2; ++h) {
            const int t = tl + h * 64;
#pragma unroll
            for (int j = 0; j < 4; ++j) {
                const int a = saddr(4 * cl4 + j, t);
                sw[a] = ((const float*)&pw[h])[j];
                sk[a] = ((const float*)&pk[h])[j];
                sv[a] = ((const float*)&pv[h])[j];
            }
        }

        // ---- prefetch: r for THIS tile (store stage), w/k/v for next ----
        float4 pr[2];
#pragma unroll
        for (int h = 0; h < 2; ++h)
            pr[h] = __ldcs(&r[gco + (it * TTILE + tl + h * 64) * rowF4]);
        if (it + 1 < NITER) {
#pragma unroll
            for (int h = 0; h < 2; ++h) {
                const int g = gco + ((it + 1) * TTILE + tl + h * 64) * rowF4;
                pw[h] = __ldcs(&w[g]);  pk[h] = __ldcs(&k[g]);  pv[h] = __ldcs(&v[g]);
            }
        }
        __syncthreads();   // sync1: staging visible; prior so-readers done

        // ---- per-warp serial-4 hybrid scan over 2 owned channels ----
#pragma unroll
        for (int sub = 0; sub < 2; ++sub) {
            const int ch = 2 * wid + sub;
            const int p  = ch * SROW + ((4 * lane + 24 * (ch >> 2)) & 127);
            const float4 w4 = *(const float4*)&sw[p];
            const float4 k4 = *(const float4*)&sk[p];
            const float4 v4 = *(const float4*)&sv[p];

            float d[4], e[4], x[4];
#pragma unroll
            for (int i = 0; i < 4; ++i) {
                const float wv = ((const float*)&w4)[i];
                const float kv = ((const float*)&k4)[i];
                const float vv = ((const float*)&v4)[i];
                d[i] = __expf(-__expf(wv));
                e[i] = __expf(kv);
                x[i] = e[i] * vv;
            }

            // lane-local composition of its 4 steps (pairwise)
            const float D01 = d[0] * d[1];
            const float A01 = fmaf(x[0], d[1], x[1]);
            const float B01 = fmaf(e[0], d[1], e[1]);
            const float D23 = d[2] * d[3];
            const float A23 = fmaf(x[2], d[3], x[3]);
            const float B23 = fmaf(e[2], d[3], e[3]);
            float D  = D01 * D23;
            float A  = fmaf(A01, D23, A23);
            float Bv = fmaf(B01, D23, B23);

            // inclusive Kogge-Stone over lane aggregates
#pragma unroll
            for (int s = 1; s < 32; s <<= 1) {
                const float Dp = __shfl_up_sync(0xffffffffu, D, s);
                const float Ap = __shfl_up_sync(0xffffffffu, A, s);
                const float Bp = __shfl_up_sync(0xffffffffu, Bv, s);
                if (lane >= s) {
                    A  = fmaf(Ap, D, A);
                    Bv = fmaf(Bp, D, Bv);
                    D *= Dp;
                }
            }
            // exclusive prefix for this lane
            float Dx = __shfl_up_sync(0xffffffffu, D, 1);
            float Ax = __shfl_up_sync(0xffffffffu, A, 1);
            float Bx = __shfl_up_sync(0xffffffffu, Bv, 1);
            if (lane == 0) { Dx = 1.f; Ax = 0.f; Bx = 0.f; }
            float ain = fmaf(aC[sub], Dx, Ax);
            float bin = fmaf(bC[sub], Dx, Bx);

            // carry update from lane 31 inclusive aggregate
            const float D31 = __shfl_sync(0xffffffffu, D, 31);
            const float A31 = __shfl_sync(0xffffffffu, A, 31);
            const float B31 = __shfl_sync(0xffffffffu, Bv, 31);
            aC[sub] = fmaf(aC[sub], D31, A31);
            bC[sub] = fmaf(bC[sub], D31, B31);

            // replay the 4 local steps, emit a/(b+eps) as one STS.128
            float4 o4;
#pragma unroll
            for (int i = 0; i < 4; ++i) {
                ain = fmaf(ain, d[i], x[i]);
                bin = fmaf(bin, d[i], e[i]);
                ((float*)&o4)[i] = __fdividef(ain, bin + WKV_EPS);
            }
            *(float4*)&so[p] = o4;
        }
        __syncthreads();   // sync2: so complete; scan reads of this buf done

        // ---- readback + sigmoid(r) + coalesced float4 store ----
#pragma unroll
        for (int h = 0; h < 2; ++h) {
            const int t = tl + h * 64;
            float4 o;
#pragma unroll
            for (int j = 0; j < 4; ++j)
                ((float*)&o)[j] = so[saddr(4 * cl4 + j, t)];
            o.x = __fdividef(o.x, 1.f + __expf(-pr[h].x));
            o.y = __fdividef(o.y, 1.f + __expf(-pr[h].y));
            o.z = __fdividef(o.z, 1.f + __expf(-pr[h].z));
            o.w = __fdividef(o.w, 1.f + __expf(-pr[h].w));
            __stcs(&out[gco + (it * TTILE + t) * rowF4], o);
        }
        // so is re-written only after the next iteration's sync1.
    }
}

extern "C" void kernel_launch(void* const* d_in, const int* in_sizes, int n_in,
                              void* d_out, int out_size) {
    const float4* r = (const float4*)d_in[0];
    const float4* w = (const float4*)d_in[1];
    const float4* k = (const float4*)d_in[2];
    const float4* v = (const float4*)d_in[3];
    float4* o = (float4*)d_out;

    cudaFuncSetAttribute(wkv_scan5,
                         cudaFuncAttributeMaxDynamicSharedMemorySize, SMEMB);
    const int grid = B_ * (C_ / CBLK);    // 512 CTAs
    wkv_scan5<<<grid, THREADS, SMEMB>>>(r, w, k, v, o);
}

// round 12
// speedup vs baseline: 1.4642x; 1.4642x over previous
#include <cuda_runtime.h>

// RWKV WKV single-pass warp-scan, v6.
//   a_t = d_t a_{t-1} + ek_t v_t ; b_t = d_t b_{t-1} + ek_t
//   out = sigmoid(r) * a/(b+eps),  d = exp(-exp(w)), ek = exp(k)
//
// v2 (151.5us) geometry — CBLK=32 (128B-contiguous global runs), TTILE=64,
// serial-2 scan, double-buffered smem, verified skewed bank layout — but with
// 512 threads/CTA (16 warps -> ~28 warps/SM at 2 CTAs/SM, 2x v2 residency)
// and r kept out of smem (sigmoid applied at store stage from registers).

#define B_      8
#define T_      4096
#define C_      1024
#define CBLK    32
#define TTILE   64
#define NITER   (T_ / TTILE)      // 64
#define THREADS 512
#define SROW    66                // even stride + skew -> conflict-free (v2)
#define REGF    (CBLK * SROW)     // 2112 floats per region
#define SMEMB   (7 * REGF * 4)    // w,k,v x 2 bufs + so = 59136 B
#define WKV_EPS 1e-6f

// v2-verified skewed transpose address (conflict-free for writer pattern
// (12*cl4 + 2j + tl) mod 32, scan-side LDS.64, and readback).
__device__ __forceinline__ int saddr(int ch, int t) {
    return ch * SROW + ((t + 4 * (ch >> 2)) & 63);
}

__global__ void __launch_bounds__(THREADS, 2)
wkv_scan6(const float4* __restrict__ r, const float4* __restrict__ w,
          const float4* __restrict__ k, const float4* __restrict__ v,
          float4* __restrict__ out) {
    extern __shared__ float S[];
    float* so = S + 6 * REGF;     // output region (single buffer)

    const int tid  = threadIdx.x;
    const int lane = tid & 31;
    const int wid  = tid >> 5;    // 0..15: warp owns channels 2*wid, 2*wid+1
    const int cl4  = tid & 7;     // float4 column (8 x 16B = 32 ch = 128B run)
    const int tl   = tid >> 3;    // 0..63: one t-row per thread

    const int b  = blockIdx.x >> 5;               // 8 batches
    const int c0 = (blockIdx.x & 31) * CBLK;      // 32 channel blocks
    const int rowF4 = C_ / 4;                     // 256 float4 per time row
    const int gco   = (b * T_) * rowF4 + (c0 >> 2) + cl4;

    // Prefetch tile 0 (raw w,k,v; one float4 row per stream per thread).
    float4 pw = __ldcs(&w[gco + tl * rowF4]);
    float4 pk = __ldcs(&k[gco + tl * rowF4]);
    float4 pv = __ldcs(&v[gco + tl * rowF4]);

    float aC[2] = {0.f, 0.f};
    float bC[2] = {0.f, 0.f};

    for (int it = 0; it < NITER; ++it) {
        const int bf = it & 1;
        float* sw = S + (0 * 2 + bf) * REGF;
        float* sk = S + (1 * 2 + bf) * REGF;
        float* sv = S + (2 * 2 + bf) * REGF;

        // ---- stage current tile (transposed, skewed; banks distinct) ----
#pragma unroll
        for (int j = 0; j < 4; ++j) {
            const int a = saddr(4 * cl4 + j, tl);
            sw[a] = ((const float*)&pw)[j];
            sk[a] = ((const float*)&pk)[j];
            sv[a] = ((const float*)&pv)[j];
        }

        // ---- prefetch: r for THIS tile (store stage), w/k/v for next ----
        float4 pr = __ldcs(&r[gco + (it * TTILE + tl) * rowF4]);
        if (it + 1 < NITER) {
            const int g = gco + ((it + 1) * TTILE + tl) * rowF4;
            pw = __ldcs(&w[g]);  pk = __ldcs(&k[g]);  pv = __ldcs(&v[g]);
        }
        __syncthreads();   // sync1: staging visible; prior so-readers done

        // ---- per-warp serial-2 hybrid scan over 2 owned channels ----
#pragma unroll
        for (int sub = 0; sub < 2; ++sub) {
            const int ch = 2 * wid + sub;
            const int p  = saddr(ch, 2 * lane);    // 8B-aligned LDS.64
            const float2 w2 = *(const float2*)&sw[p];
            const float2 k2 = *(const float2*)&sk[p];
            const float2 v2 = *(const float2*)&sv[p];

            const float d0  = __expf(-__expf(w2.x));
            const float d1  = __expf(-__expf(w2.y));
            const float e0  = __expf(k2.x);
            const float e1  = __expf(k2.y);
            const float ev0 = e0 * v2.x;
            const float ev1 = e1 * v2.y;

            // lane-local composition of its 2 steps
            float D  = d0 * d1;
            float A  = fmaf(ev0, d1, ev1);
            float Bv = fmaf(e0, d1, e1);

            // inclusive Kogge-Stone over lane aggregates
#pragma unroll
            for (int s = 1; s < 32; s <<= 1) {
                const float Dp = __shfl_up_sync(0xffffffffu, D, s);
                const float Ap = __shfl_up_sync(0xffffffffu, A, s);
                const float Bp = __shfl_up_sync(0xffffffffu, Bv, s);
                if (lane >= s) {
                    A  = fmaf(Ap, D, A);
                    Bv = fmaf(Bp, D, Bv);
                    D *= Dp;
                }
            }
            // exclusive prefix for this lane
            float Dx = __shfl_up_sync(0xffffffffu, D, 1);
            float Ax = __shfl_up_sync(0xffffffffu, A, 1);
            float Bx = __shfl_up_sync(0xffffffffu, Bv, 1);
            if (lane == 0) { Dx = 1.f; Ax = 0.f; Bx = 0.f; }
            const float Ain = fmaf(aC[sub], Dx, Ax);
            const float Bin = fmaf(bC[sub], Dx, Bx);

            // carry update from lane 31 inclusive aggregate
            const float D31 = __shfl_sync(0xffffffffu, D, 31);
            const float A31 = __shfl_sync(0xffffffffu, A, 31);
            const float B31 = __shfl_sync(0xffffffffu, Bv, 31);
            aC[sub] = fmaf(aC[sub], D31, A31);
            bC[sub] = fmaf(bC[sub], D31, B31);

            // replay the 2 local steps, emit a/(b+eps)
            const float a0 = fmaf(Ain, d0, ev0);
            const float b0 = fmaf(Bin, d0, e0);
            const float a1 = fmaf(a0, d1, ev1);
            const float b1 = fmaf(b0, d1, e1);
            *(float2*)&so[p] = make_float2(__fdividef(a0, b0 + WKV_EPS),
                                           __fdividef(a1, b1 + WKV_EPS));
        }
        __syncthreads();   // sync2: so complete; scan reads of this buf done

        // ---- readback + sigmoid(r) + coalesced float4 store ----
        float4 o;
#pragma unroll
        for (int j = 0; j < 4; ++j)
            ((float*)&o)[j] = so[saddr(4 * cl4 + j, tl)];
        o.x = __fdividef(o.x, 1.f + __expf(-pr.x));
        o.y = __fdividef(o.y, 1.f + __expf(-pr.y));
        o.z = __fdividef(o.z, 1.f + __expf(-pr.z));
        o.w = __fdividef(o.w, 1.f + __expf(-pr.w));
        __stcs(&out[gco + (it * TTILE + tl) * rowF4], o);
        // so is re-written only after the next iteration's sync1.
    }
}

extern "C" void kernel_launch(void* const* d_in, const int* in_sizes, int n_in,
                              void* d_out, int out_size) {
    const float4* r = (const float4*)d_in[0];
    const float4* w = (const float4*)d_in[1];
    const float4* k = (const float4*)d_in[2];
    const float4* v = (const float4*)d_in[3];
    float4* o = (float4*)d_out;

    cudaFuncSetAttribute(wkv_scan6,
                         cudaFuncAttributeMaxDynamicSharedMemorySize, SMEMB);
    const int grid = B_ * (C_ / CBLK);    // 256 CTAs
    wkv_scan6<<<grid, THREADS, SMEMB>>>(r, w, k, v, o);
}

// round 13
// speedup vs baseline: 1.5543x; 1.0615x over previous
#include <cuda_runtime.h>

// RWKV WKV single-pass warp-scan, v7: v6 + software-pipelined epilogue,
// ONE __syncthreads per iteration (readback of tile it-1 overlaps scan of it).
//   a_t = d_t a_{t-1} + ek_t v_t ; b_t = d_t b_{t-1} + ek_t
//   out = sigmoid(r) * a/(b+eps),  d = exp(-exp(w)), ek = exp(k)
//
// Geometry (validated at 141.3us): CBLK=32 (128B global runs), TTILE=64,
// 512 threads (16 warps, ~28 warps/SM at 2 CTAs/SM), serial-2 KS scan,
// skewed conflict-free smem transpose, r never staged.

#define B_      8
#define T_      4096
#define C_      1024
#define CBLK    32
#define TTILE   64
#define NITER   (T_ / TTILE)      // 64
#define THREADS 512
#define SROW    66                // even stride + skew -> conflict-free
#define REGF    (CBLK * SROW)     // 2112 floats per region
#define SMEMB   (8 * REGF * 4)    // w,k,v,so x 2 buffers = 67584 B
#define WKV_EPS 1e-6f

// v2/v6-verified skewed transpose address.
__device__ __forceinline__ int saddr(int ch, int t) {
    return ch * SROW + ((t + 4 * (ch >> 2)) & 63);
}

__global__ void __launch_bounds__(THREADS, 2)
wkv_scan7(const float4* __restrict__ r, const float4* __restrict__ w,
          const float4* __restrict__ k, const float4* __restrict__ v,
          float4* __restrict__ out) {
    extern __shared__ float S[];

    const int tid  = threadIdx.x;
    const int lane = tid & 31;
    const int wid  = tid >> 5;    // 0..15: warp owns channels 2*wid, 2*wid+1
    const int cl4  = tid & 7;     // float4 column (8 x 16B = 128B run)
    const int tl   = tid >> 3;    // 0..63: one t-row per thread

    const int b  = blockIdx.x >> 5;               // 8 batches
    const int c0 = (blockIdx.x & 31) * CBLK;      // 32 channel blocks
    const int rowF4 = C_ / 4;                     // 256 float4 per time row
    const int gco   = (b * T_) * rowF4 + (c0 >> 2) + cl4;

    // Prefetch tile 0 (raw w,k,v).
    float4 pw = __ldcs(&w[gco + tl * rowF4]);
    float4 pk = __ldcs(&k[gco + tl * rowF4]);
    float4 pv = __ldcs(&v[gco + tl * rowF4]);
    float4 prPrev;                                // r for tile it-1

    float aC[2] = {0.f, 0.f};
    float bC[2] = {0.f, 0.f};

    for (int it = 0; it < NITER; ++it) {
        const int bf = it & 1;
        float* sw = S + (0 + bf) * REGF;
        float* sk = S + (2 + bf) * REGF;
        float* sv = S + (4 + bf) * REGF;
        float* so = S + (6 + bf) * REGF;
        float* soPrev = S + (6 + (1 - bf)) * REGF;

        // ---- stage current tile (transposed, skewed) ----
#pragma unroll
        for (int j = 0; j < 4; ++j) {
            const int a = saddr(4 * cl4 + j, tl);
            sw[a] = ((const float*)&pw)[j];
            sk[a] = ((const float*)&pk)[j];
            sv[a] = ((const float*)&pv)[j];
        }

        // ---- prefetch: r for THIS tile, w/k/v for the next ----
        float4 pr = __ldcs(&r[gco + (it * TTILE + tl) * rowF4]);
        if (it + 1 < NITER) {
            const int g = gco + ((it + 1) * TTILE + tl) * rowF4;
            pw = __ldcs(&w[g]);  pk = __ldcs(&k[g]);  pv = __ldcs(&v[g]);
        }
        __syncthreads();   // single barrier: staging visible, prior phase done

        // ---- per-warp serial-2 hybrid scan over 2 owned channels ----
#pragma unroll
        for (int sub = 0; sub < 2; ++sub) {
            const int ch = 2 * wid + sub;
            const int p  = saddr(ch, 2 * lane);    // 8B-aligned LDS.64
            const float2 w2 = *(const float2*)&sw[p];
            const float2 k2 = *(const float2*)&sk[p];
            const float2 v2 = *(const float2*)&sv[p];

            const float d0  = __expf(-__expf(w2.x));
            const float d1  = __expf(-__expf(w2.y));
            const float e0  = __expf(k2.x);
            const float e1  = __expf(k2.y);
            const float ev0 = e0 * v2.x;
            const float ev1 = e1 * v2.y;

            // lane-local composition of its 2 steps
            float D  = d0 * d1;
            float A  = fmaf(ev0, d1, ev1);
            float Bv = fmaf(e0, d1, e1);

            // inclusive Kogge-Stone over lane aggregates
#pragma unroll
            for (int s = 1; s < 32; s <<= 1) {
                const float Dp = __shfl_up_sync(0xffffffffu, D, s);
                const float Ap = __shfl_up_sync(0xffffffffu, A, s);
                const float Bp = __shfl_up_sync(0xffffffffu, Bv, s);
                if (lane >= s) {
                    A  = fmaf(Ap, D, A);
                    Bv = fmaf(Bp, D, Bv);
                    D *= Dp;
                }
            }
            // exclusive prefix for this lane
            float Dx = __shfl_up_sync(0xffffffffu, D, 1);
            float Ax = __shfl_up_sync(0xffffffffu, A, 1);
            float Bx = __shfl_up_sync(0xffffffffu, Bv, 1);
            if (lane == 0) { Dx = 1.f; Ax = 0.f; Bx = 0.f; }
            const float Ain = fmaf(aC[sub], Dx, Ax);
            const float Bin = fmaf(bC[sub], Dx, Bx);

            // carry update from lane 31 inclusive aggregate
            const float D31 = __shfl_sync(0xffffffffu, D, 31);
            const float A31 = __shfl_sync(0xffffffffu, A, 31);
            const float B31 = __shfl_sync(0xffffffffu, Bv, 31);
            aC[sub] = fmaf(aC[sub], D31, A31);
            bC[sub] = fmaf(bC[sub], D31, B31);

            // replay the 2 local steps, emit a/(b+eps)
            const float a0 = fmaf(Ain, d0, ev0);
            const float b0 = fmaf(Bin, d0, e0);
            const float a1 = fmaf(a0, d1, ev1);
            const float b1 = fmaf(b0, d1, e1);
            *(float2*)&so[p] = make_float2(__fdividef(a0, b0 + WKV_EPS),
                                           __fdividef(a1, b1 + WKV_EPS));
        }

        // ---- pipelined readback of tile it-1 (other buffer; no barrier) ----
        if (it > 0) {
            float4 o;
#pragma unroll
            for (int j = 0; j < 4; ++j)
                ((float*)&o)[j] = soPrev[saddr(4 * cl4 + j, tl)];
            o.x = __fdividef(o.x, 1.f + __expf(-prPrev.x));
            o.y = __fdividef(o.y, 1.f + __expf(-prPrev.y));
            o.z = __fdividef(o.z, 1.f + __expf(-prPrev.z));
            o.w = __fdividef(o.w, 1.f + __expf(-prPrev.w));
            __stcs(&out[gco + ((it - 1) * TTILE + tl) * rowF4], o);
        }
        prPrev = pr;
    }

    // ---- final readback: tile NITER-1 lives in buffer (NITER-1)&1 = 1 ----
    __syncthreads();
    {
        float* soLast = S + (6 + ((NITER - 1) & 1)) * REGF;
        float4 o;
#pragma unroll
        for (int j = 0; j < 4; ++j)
            ((float*)&o)[j] = soLast[saddr(4 * cl4 + j, tl)];
        o.x = __fdividef(o.x, 1.f + __expf(-prPrev.x));
        o.y = __fdividef(o.y, 1.f + __expf(-prPrev.y));
        o.z = __fdividef(o.z, 1.f + __expf(-prPrev.z));
        o.w = __fdividef(o.w, 1.f + __expf(-prPrev.w));
        __stcs(&out[gco + ((NITER - 1) * TTILE + tl) * rowF4], o);
    }
}

extern "C" void kernel_launch(void* const* d_in, const int* in_sizes, int n_in,
                              void* d_out, int out_size) {
    const float4* r = (const float4*)d_in[0];
    const float4* w = (const float4*)d_in[1];
    const float4* k = (const float4*)d_in[2];
    const float4* v = (const float4*)d_in[3];
    float4* o = (float4*)d_out;

    cudaFuncSetAttribute(wkv_scan7,
                         cudaFuncAttributeMaxDynamicSharedMemorySize, SMEMB);
    const int grid = B_ * (C_ / CBLK);    // 256 CTAs
    wkv_scan7<<<grid, THREADS, SMEMB>>>(r, w, k, v, o);
}

// round 14
// speedup vs baseline: 1.8041x; 1.1607x over previous
#include <cuda_runtime.h>

// RWKV WKV single-pass warp-scan, v8: v7 pipeline + segmented serial-4 scan.
//   a_t = d_t a_{t-1} + ek_t v_t ; b_t = d_t b_{t-1} + ek_t
//   out = sigmoid(r) * a/(b+eps),  d = exp(-exp(w)), ek = exp(k)
//
// Warp = two 16-lane segments, one channel each; lane owns 4 consecutive
// timesteps -> width-16 Kogge-Stone (4 steps): 18 SHFL per 128 elements
// (vs 42 in v7), LDS.128/STS.128 on the scan side. Geometry otherwise v7:
// CBLK=32 (128B runs), TTILE=64, 512 thr, 1 barrier/iter, r never staged.

#define B_      8
#define T_      4096
#define C_      1024
#define CBLK    32
#define TTILE   64
#define NITER   (T_ / TTILE)      // 64
#define THREADS 512
#define SROW    68                // mult of 4 (16B-aligned rows) + skew
#define REGF    (CBLK * SROW)     // 2176 floats per region
#define SMEMB   (8 * REGF * 4)    // w,k,v,so x 2 buffers = 69632 B
#define WKV_EPS 1e-6f

// Skew 4*(ch>>2) keeps 16B alignment. Verified conflict-free:
//  writer (20*cl4+4j+tl) mod 32 all distinct; scan LDS.128 / so STS.128
//  sweep 32 consecutive rotated words per 8-lane phase; readback = writer.
__device__ __forceinline__ int saddr(int ch, int t) {
    return ch * SROW + ((t + 4 * (ch >> 2)) & 63);
}

__global__ void __launch_bounds__(THREADS, 2)
wkv_scan8(const float4* __restrict__ r, const float4* __restrict__ w,
          const float4* __restrict__ k, const float4* __restrict__ v,
          float4* __restrict__ out) {
    extern __shared__ float S[];

    const int tid  = threadIdx.x;
    const int lane = tid & 31;
    const int wid  = tid >> 5;    // 0..15
    const int seg  = lane >> 4;   // 0/1: which of the warp's 2 channels
    const int sl   = lane & 15;   // lane within segment
    const int cl4  = tid & 7;     // float4 column (8 x 16B = 128B run)
    const int tl   = tid >> 3;    // 0..63: one t-row per thread (load/store)

    const int b  = blockIdx.x >> 5;               // 8 batches
    const int c0 = (blockIdx.x & 31) * CBLK;      // 32 channel blocks
    const int rowF4 = C_ / 4;                     // 256 float4 per time row
    const int gco   = (b * T_) * rowF4 + (c0 >> 2) + cl4;

    const int chS = 2 * wid + seg;                // scan channel
    const int pS  = saddr(chS, 4 * sl);           // 16B-aligned

    // Prefetch tile 0 (raw w,k,v).
    float4 pw = __ldcs(&w[gco + tl * rowF4]);
    float4 pk = __ldcs(&k[gco + tl * rowF4]);
    float4 pv = __ldcs(&v[gco + tl * rowF4]);
    float4 prPrev;

    float aC = 0.f, bC = 0.f;     // per-lane channel carry (segment-uniform)

    for (int it = 0; it < NITER; ++it) {
        const int bf = it & 1;
        float* sw = S + (0 + bf) * REGF;
        float* sk = S + (2 + bf) * REGF;
        float* sv = S + (4 + bf) * REGF;
        float* so = S + (6 + bf) * REGF;
        float* soPrev = S + (6 + (1 - bf)) * REGF;

        // ---- stage current tile (transposed, skewed) ----
#pragma unroll
        for (int j = 0; j < 4; ++j) {
            const int a = saddr(4 * cl4 + j, tl);
            sw[a] = ((const float*)&pw)[j];
            sk[a] = ((const float*)&pk)[j];
            sv[a] = ((const float*)&pv)[j];
        }

        // ---- prefetch: r for THIS tile, w/k/v for the next ----
        float4 pr = __ldcs(&r[gco + (it * TTILE + tl) * rowF4]);
        if (it + 1 < NITER) {
            const int g = gco + ((it + 1) * TTILE + tl) * rowF4;
            pw = __ldcs(&w[g]);  pk = __ldcs(&k[g]);  pv = __ldcs(&v[g]);
        }
        __syncthreads();   // single barrier per iteration

        // ---- segmented serial-4 scan (one channel per 16-lane segment) ----
        {
            const float4 w4 = *(const float4*)&sw[pS];
            const float4 k4 = *(const float4*)&sk[pS];
            const float4 v4 = *(const float4*)&sv[pS];

            float d[4], e[4], x[4];
#pragma unroll
            for (int i = 0; i < 4; ++i) {
                d[i] = __expf(-__expf(((const float*)&w4)[i]));
                e[i] = __expf(((const float*)&k4)[i]);
                x[i] = e[i] * ((const float*)&v4)[i];
            }

            // lane-local composition of 4 steps (pairwise tree)
            const float D01 = d[0] * d[1];
            const float A01 = fmaf(x[0], d[1], x[1]);
            const float B01 = fmaf(e[0], d[1], e[1]);
            const float D23 = d[2] * d[3];
            const float A23 = fmaf(x[2], d[3], x[3]);
            const float B23 = fmaf(e[2], d[3], e[3]);
            float D  = D01 * D23;
            float A  = fmaf(A01, D23, A23);
            float Bv = fmaf(B01, D23, B23);

            // width-16 inclusive Kogge-Stone over lane aggregates
#pragma unroll
            for (int s = 1; s < 16; s <<= 1) {
                const float Dp = __shfl_up_sync(0xffffffffu, D, s, 16);
                const float Ap = __shfl_up_sync(0xffffffffu, A, s, 16);
                const float Bp = __shfl_up_sync(0xffffffffu, Bv, s, 16);
                if (sl >= s) {
                    A  = fmaf(Ap, D, A);
                    Bv = fmaf(Bp, D, Bv);
                    D *= Dp;
                }
            }
            // exclusive prefix for this lane (within segment)
            float Dx = __shfl_up_sync(0xffffffffu, D, 1, 16);
            float Ax = __shfl_up_sync(0xffffffffu, A, 1, 16);
            float Bx = __shfl_up_sync(0xffffffffu, Bv, 1, 16);
            if (sl == 0) { Dx = 1.f; Ax = 0.f; Bx = 0.f; }
            float ain = fmaf(aC, Dx, Ax);
            float bin = fmaf(bC, Dx, Bx);

            // carry update from segment lane 15 inclusive aggregate
            const float D15 = __shfl_sync(0xffffffffu, D, 15, 16);
            const float A15 = __shfl_sync(0xffffffffu, A, 15, 16);
            const float B15 = __shfl_sync(0xffffffffu, Bv, 15, 16);
            aC = fmaf(aC, D15, A15);
            bC = fmaf(bC, D15, B15);

            // replay 4 local steps, emit a/(b+eps) as one STS.128
            float4 o4;
#pragma unroll
            for (int i = 0; i < 4; ++i) {
                ain = fmaf(ain, d[i], x[i]);
                bin = fmaf(bin, d[i], e[i]);
                ((float*)&o4)[i] = __fdividef(ain, bin + WKV_EPS);
            }
            *(float4*)&so[pS] = o4;
        }

        // ---- pipelined readback of tile it-1 (other buffer; no barrier) ----
        if (it > 0) {
            float4 o;
#pragma unroll
            for (int j = 0; j < 4; ++j)
                ((float*)&o)[j] = soPrev[saddr(4 * cl4 + j, tl)];
            o.x = __fdividef(o.x, 1.f + __expf(-prPrev.x));
            o.y = __fdividef(o.y, 1.f + __expf(-prPrev.y));
            o.z = __fdividef(o.z, 1.f + __expf(-prPrev.z));
            o.w = __fdividef(o.w, 1.f + __expf(-prPrev.w));
            __stcs(&out[gco + ((it - 1) * TTILE + tl) * rowF4], o);
        }
        prPrev = pr;
    }

    // ---- final readback: tile NITER-1 lives in buffer (NITER-1)&1 ----
    __syncthreads();
    {
        float* soLast = S + (6 + ((NITER - 1) & 1)) * REGF;
        float4 o;
#pragma unroll
        for (int j = 0; j < 4; ++j)
            ((float*)&o)[j] = soLast[saddr(4 * cl4 + j, tl)];
        o.x = __fdividef(o.x, 1.f + __expf(-prPrev.x));
        o.y = __fdividef(o.y, 1.f + __expf(-prPrev.y));
        o.z = __fdividef(o.z, 1.f + __expf(-prPrev.z));
        o.w = __fdividef(o.w, 1.f + __expf(-prPrev.w));
        __stcs(&out[gco + ((NITER - 1) * TTILE + tl) * rowF4], o);
    }
}

extern "C" void kernel_launch(void* const* d_in, const int* in_sizes, int n_in,
                              void* d_out, int out_size) {
    const float4* r = (const float4*)d_in[0];
    const float4* w = (const float4*)d_in[1];
    const float4* k = (const float4*)d_in[2];
    const float4* v = (const float4*)d_in[3];
    float4* o = (float4*)d_out;

    cudaFuncSetAttribute(wkv_scan8,
                         cudaFuncAttributeMaxDynamicSharedMemorySize, SMEMB);
    const int grid = B_ * (C_ / CBLK);    // 256 CTAs
    wkv_scan8<<<grid, THREADS, SMEMB>>>(r, w, k, v, o);
}